// round 16
// baseline (speedup 1.0000x reference)
#include <cuda_runtime.h>
#include <cuda_fp16.h>
#include <cstdint>

// Problem constants
#define Bsz 256
#define Nn  512
#define Ff  256
#define Hh  256
#define NSTAGE 5
#define LN_EPS 1e-5f

typedef unsigned long long ull;
typedef unsigned short ushort_t;

// ---------------- scratch (device globals; no allocations allowed) ----------
__device__ __half g_supH[(size_t)Bsz * Hh * Nn];   // support hi, [b][h][node]
__device__ __half g_supL[(size_t)Bsz * Hh * Nn];   // support lo
__device__ __half g_w0H [Hh * Ff];                 // W0^T hi, [h][f]
__device__ __half g_w0L [Hh * Ff];
__device__ float  g_out [(size_t)Bsz * Nn * Hh];   // relu(LN0(x))+b1 rows
__device__ ull    g_amax[Bsz * NSTAGE];            // packed argmax keys
__device__ float  g_zsum[Bsz * Hh];

// ---------------- helpers ---------------------------------------------------
__device__ __forceinline__ unsigned int f2ord(float f) {
    unsigned int u = __float_as_uint(f);
    return (u & 0x80000000u) ? ~u : (u | 0x80000000u);
}

__device__ __forceinline__ uint32_t smem_u32(const void* p) {
    uint32_t a;
    asm("{ .reg .u64 t; cvta.to.shared.u64 t, %1; cvt.u32.u64 %0, t; }" : "=r"(a) : "l"(p));
    return a;
}

__device__ __forceinline__ void cpasync16(uint32_t dst, const void* src) {
    asm volatile("cp.async.ca.shared.global [%0], [%1], 16;"
                 :: "r"(dst), "l"(src) : "memory");
}
__device__ __forceinline__ void cp_commit() {
    asm volatile("cp.async.commit_group;" ::: "memory");
}

__device__ __forceinline__ float block_sum256(float v, float* sbuf) {
    #pragma unroll
    for (int o = 16; o > 0; o >>= 1) v += __shfl_xor_sync(0xffffffffu, v, o);
    if ((threadIdx.x & 31) == 0) sbuf[threadIdx.x >> 5] = v;
    __syncthreads();
    float t = 0.f;
    if (threadIdx.x < 32) {
        t = (threadIdx.x < 8) ? sbuf[threadIdx.x] : 0.f;
        #pragma unroll
        for (int o = 4; o > 0; o >>= 1) t += __shfl_xor_sync(0xffffffffu, t, o);
        if (threadIdx.x == 0) sbuf[0] = t;
    }
    __syncthreads();
    t = sbuf[0];
    __syncthreads();
    return t;
}

// m16n8k16 f16 mma, fp32 accumulate
__device__ __forceinline__ void mma16816(float* c, const uint32_t* a,
                                         uint32_t b0, uint32_t b1) {
    asm volatile(
        "mma.sync.aligned.m16n8k16.row.col.f32.f16.f16.f32 "
        "{%0,%1,%2,%3}, {%4,%5,%6,%7}, {%8,%9}, {%0,%1,%2,%3};"
        : "+f"(c[0]), "+f"(c[1]), "+f"(c[2]), "+f"(c[3])
        : "r"(a[0]), "r"(a[1]), "r"(a[2]), "r"(a[3]), "r"(b0), "r"(b1));
}

// split one f32 into (hi fp16, lo fp16 = rn(x - hi))
__device__ __forceinline__ void split16(float x, ushort_t& h, ushort_t& l) {
    __half hh = __float2half_rn(x);
    float r = x - __half2float(hh);
    h = __half_as_ushort(hh);
    l = __half_as_ushort(__float2half_rn(r));
}

// ---------------- init / W0 split+transpose ---------------------------------
__global__ void init_kernel() {
    int i = blockIdx.x * blockDim.x + threadIdx.x;
    if (i < Bsz * Hh) g_zsum[i] = 0.f;
    if (i < Bsz * NSTAGE) g_amax[i] = 0ull;
}

__global__ void w0split_kernel(const float* __restrict__ W0) {
    __shared__ float t[32][33];
    int bx = blockIdx.x & 7;       // h tile
    int by = blockIdx.x >> 3;      // f tile
    int c = (threadIdx.x >> 5) * 4, d = threadIdx.x & 31;
    #pragma unroll
    for (int i = 0; i < 4; i++)
        t[c + i][d] = W0[(by * 32 + c + i) * Hh + bx * 32 + d];  // t[f_l][h_l]
    __syncthreads();
    #pragma unroll
    for (int i = 0; i < 4; i++) {
        float v = t[d][c + i];     // f_l=d, h_l=c+i
        ushort_t h, l;
        split16(v, h, l);
        int o = (bx * 32 + c + i) * Ff + by * 32 + d;
        g_w0H[o] = __ushort_as_half(h);
        g_w0L[o] = __ushort_as_half(l);
    }
}

// ---------------- HMMA split-fp16 GEMM, 2-stage cp.async pipeline -----------
// Tile: BM=64 x BN=256 (full H), BK=32 halfs. 256 threads, 8 warps (2m x 4n).
// mode 0: C = features[131072,256] @ W0  -> g_supH/g_supL, [b][h][node] fp16
// mode 1: x = adj[b] @ support[b]        -> fused +b0, LN0, relu, +b1,
//         score+argmax, writes g_out.
//
// staging stage (word units, pitch PW=20 words per 32-half row):
//   AHI 0..1280, ALO 1280.., BHI 2560.., BLO 7680..  -> 12800 words (51200 B)
// two stages = 102400 B dynamic; epilogue xs aliases offset 0.
#define SMEM_DYN 102400
#define PW  20
#define PXS 260
#define STG_W 12800
#define AHI_W 0
#define ALO_W 1280
#define BHI_W 2560
#define BLO_W 7680

__global__ __launch_bounds__(256, 2)
void gemm_mma(const float* __restrict__ Aglob, int mode,
              const float* __restrict__ b0p, const float* __restrict__ g0p,
              const float* __restrict__ be0p, const float* __restrict__ b1p,
              const int* __restrict__ sidp)
{
    extern __shared__ char dynsm[];
    __shared__ float sPar[4][256];         // b0, g0, be0, b1 (mode 1)

    uint32_t* W  = (uint32_t*)dynsm;
    float*    xs = (float*)dynsm;
    const uint32_t sb32 = smem_u32(dynsm);

    const int tid  = threadIdx.x;
    const int wid  = tid >> 5;
    const int lane = tid & 31;
    const int g    = lane >> 2;
    const int tg   = lane & 3;
    const int mBase = (wid >> 2) * 32;     // 0 or 32
    const int nBase = (wid & 3) * 64;      // 0,64,128,192

    int K, bat, nrow0;
    const float*  Ap;
    const __half* BH;
    const __half* BL;
    int bstr;
    if (mode) {
        K = Nn;
        bat   = blockIdx.x >> 3;
        nrow0 = (blockIdx.x & 7) * 64;
        Ap = Aglob + ((size_t)bat * Nn + nrow0) * (size_t)Nn;
        BH = g_supH + (size_t)bat * Hh * Nn;
        BL = g_supL + (size_t)bat * Hh * Nn;
        bstr = Nn;
        sPar[0][tid] = b0p[tid];  sPar[1][tid] = g0p[tid];
        sPar[2][tid] = be0p[tid]; sPar[3][tid] = b1p[tid];
    } else {
        K = Ff;
        bat   = blockIdx.x >> 3;
        nrow0 = (blockIdx.x & 7) * 64;
        Ap = Aglob + (size_t)blockIdx.x * 64 * (size_t)Ff;
        BH = g_w0H;  BL = g_w0L;
        bstr = Ff;
    }

    // per-thread staging coordinates
    const int arow0 = tid >> 3, akq0 = tid & 7;           // A iter 0
    const int arow1 = (tid + 256) >> 3, akq1 = tid & 7;   // A iter 1
    const int bh0 = tid >> 2, bq = tid & 3;               // B: 4 h-rows per it

    float acc[2][8][4];
    #pragma unroll
    for (int mt = 0; mt < 2; mt++)
        #pragma unroll
        for (int nt = 0; nt < 8; nt++)
            #pragma unroll
            for (int e = 0; e < 4; e++) acc[mt][nt][e] = 0.f;

    const int NCH = K >> 5;

    // issue B cp.asyncs for chunk (k0) into stage s
    auto stageB = [&](int k0, int s) {
        const uint32_t base = sb32 + (uint32_t)(s * STG_W) * 4;
        #pragma unroll
        for (int it = 0; it < 4; it++) {
            int h = bh0 + (it << 6);
            uint32_t dof = (uint32_t)(h * PW + (bq << 2)) * 4;
            const __half* sh = BH + (size_t)h * bstr + k0 + (bq << 3);
            const __half* sl = BL + (size_t)h * bstr + k0 + (bq << 3);
            cpasync16(base + BHI_W * 4 + dof, sh);
            cpasync16(base + BLO_W * 4 + dof, sl);
        }
        cp_commit();
    };

    // ---- preload chunk 0 ----
    float4 av0 = *(const float4*)(Ap + (size_t)arow0 * K + (akq0 << 2));
    float4 av1 = *(const float4*)(Ap + (size_t)arow1 * K + (akq1 << 2));
    stageB(0, 0);

    for (int c = 0; c < NCH; c++) {
        const int cur = c & 1;
        uint32_t* Ws = W + cur * STG_W;

        // ---- split + STS A(c) from regs ----
        {
            ushort_t hx, lx, hy, ly, hz, lz, hw, lw;
            split16(av0.x, hx, lx); split16(av0.y, hy, ly);
            split16(av0.z, hz, lz); split16(av0.w, hw, lw);
            int w = arow0 * PW + (akq0 << 1);
            Ws[AHI_W + w]     = (uint32_t)hx | ((uint32_t)hy << 16);
            Ws[AHI_W + w + 1] = (uint32_t)hz | ((uint32_t)hw << 16);
            Ws[ALO_W + w]     = (uint32_t)lx | ((uint32_t)ly << 16);
            Ws[ALO_W + w + 1] = (uint32_t)lz | ((uint32_t)lw << 16);
            split16(av1.x, hx, lx); split16(av1.y, hy, ly);
            split16(av1.z, hz, lz); split16(av1.w, hw, lw);
            w = arow1 * PW + (akq1 << 1);
            Ws[AHI_W + w]     = (uint32_t)hx | ((uint32_t)hy << 16);
            Ws[AHI_W + w + 1] = (uint32_t)hz | ((uint32_t)hw << 16);
            Ws[ALO_W + w]     = (uint32_t)lx | ((uint32_t)ly << 16);
            Ws[ALO_W + w + 1] = (uint32_t)lz | ((uint32_t)lw << 16);
        }

        // ---- issue next chunk's loads (overlap with this chunk's MMA) ----
        if (c + 1 < NCH) {
            const int k1 = (c + 1) << 5;
            av0 = *(const float4*)(Ap + (size_t)arow0 * K + k1 + (akq0 << 2));
            av1 = *(const float4*)(Ap + (size_t)arow1 * K + k1 + (akq1 << 2));
            stageB(k1, 1 - cur);
            asm volatile("cp.async.wait_group 1;" ::: "memory");
        } else {
            asm volatile("cp.async.wait_group 0;" ::: "memory");
        }
        __syncthreads();

        // ---- mma on stage cur: 2 k16 steps ----
        #pragma unroll
        for (int ks = 0; ks < 2; ks++) {
            const int kw = ks << 3;
            uint32_t aH[2][4], aL[2][4];
            #pragma unroll
            for (int mt = 0; mt < 2; mt++) {
                int m0 = (mBase + mt * 16 + g) * PW + kw + tg;
                int m8 = m0 + 8 * PW;
                aH[mt][0] = Ws[AHI_W + m0];     aH[mt][1] = Ws[AHI_W + m8];
                aH[mt][2] = Ws[AHI_W + m0 + 4]; aH[mt][3] = Ws[AHI_W + m8 + 4];
                aL[mt][0] = Ws[ALO_W + m0];     aL[mt][1] = Ws[ALO_W + m8];
                aL[mt][2] = Ws[ALO_W + m0 + 4]; aL[mt][3] = Ws[ALO_W + m8 + 4];
            }
            #pragma unroll
            for (int nt = 0; nt < 8; nt++) {
                int nw = (nBase + nt * 8 + g) * PW + kw + tg;
                uint32_t bH0 = Ws[BHI_W + nw], bH1 = Ws[BHI_W + nw + 4];
                uint32_t bL0 = Ws[BLO_W + nw], bL1 = Ws[BLO_W + nw + 4];
                #pragma unroll
                for (int mt = 0; mt < 2; mt++) {
                    mma16816(acc[mt][nt], aH[mt], bH0, bH1);
                    mma16816(acc[mt][nt], aH[mt], bL0, bL1);
                    mma16816(acc[mt][nt], aL[mt], bH0, bH1);
                }
            }
        }
        __syncthreads();   // stage cur free for chunk c+2
    }

    if (!mode) {
        // dump acc transposed: xs[h][node] pitch 65
        #pragma unroll
        for (int mt = 0; mt < 2; mt++) {
            #pragma unroll
            for (int nt = 0; nt < 8; nt++) {
                int r0 = mBase + mt * 16 + g;
                int cc = nBase + nt * 8 + 2 * tg;
                xs[cc * 65 + r0]           = acc[mt][nt][0];
                xs[(cc + 1) * 65 + r0]     = acc[mt][nt][1];
                xs[cc * 65 + r0 + 8]       = acc[mt][nt][2];
                xs[(cc + 1) * 65 + r0 + 8] = acc[mt][nt][3];
            }
        }
        __syncthreads();
        // split + packed u32 stores to g_supH/g_supL [b][h][node]
        #pragma unroll 4
        for (int it = 0; it < 32; it++) {
            int idx = tid + (it << 8);
            int h = idx >> 5, np = idx & 31;
            float v0 = xs[h * 65 + 2 * np];
            float v1 = xs[h * 65 + 2 * np + 1];
            ushort_t h0, l0, h1, l1;
            split16(v0, h0, l0); split16(v1, h1, l1);
            size_t o = ((size_t)bat * Hh + h) * Nn + nrow0 + 2 * np;
            *(uint32_t*)(g_supH + o) = (uint32_t)h0 | ((uint32_t)h1 << 16);
            *(uint32_t*)(g_supL + o) = (uint32_t)l0 | ((uint32_t)l1 << 16);
        }
        return;
    }

    // mode 1: dump acc to xs[64][PXS], then fused epilogue
    #pragma unroll
    for (int mt = 0; mt < 2; mt++) {
        #pragma unroll
        for (int nt = 0; nt < 8; nt++) {
            int r0 = mBase + mt * 16 + g;
            int cc = nBase + nt * 8 + 2 * tg;
            xs[r0 * PXS + cc]           = acc[mt][nt][0];
            xs[r0 * PXS + cc + 1]       = acc[mt][nt][1];
            xs[(r0 + 8) * PXS + cc]     = acc[mt][nt][2];
            xs[(r0 + 8) * PXS + cc + 1] = acc[mt][nt][3];
        }
    }
    __syncthreads();

    const int c0 = lane * 8;
    #pragma unroll
    for (int j = 0; j < 8; j++) {
        const int r = wid * 8 + j;
        float v[8];
        float s = 0.f, q = 0.f;
        #pragma unroll
        for (int e = 0; e < 8; e++) {
            float x = xs[r * PXS + c0 + e] + sPar[0][c0 + e];
            v[e] = x;
            s += x; q += x * x;
        }
        #pragma unroll
        for (int o = 16; o > 0; o >>= 1) {
            s += __shfl_xor_sync(0xffffffffu, s, o);
            q += __shfl_xor_sync(0xffffffffu, q, o);
        }
        const float mean = s * (1.f / Hh);
        const float rstd = rsqrtf(q * (1.f / Hh) - mean * mean + LN_EPS);

        float sc = 0.f;
        #pragma unroll
        for (int e = 0; e < 8; e++) {
            const int cc = c0 + e;
            float y = fmaxf((v[e] - mean) * rstd * sPar[1][cc] + sPar[2][cc], 0.f)
                      + sPar[3][cc];
            v[e] = y;
            sc += y;
        }
        #pragma unroll
        for (int o = 16; o > 0; o >>= 1) sc += __shfl_xor_sync(0xffffffffu, sc, o);

        const int n_in_b = nrow0 + r;
        if (lane == 0) {
            const int s_id = sidp[bat * Nn + n_in_b];
            ull key = ((ull)f2ord(sc) << 32) |
                      (ull)(0xFFFFFFFFu - (unsigned)n_in_b);  // lower idx wins
            atomicMax(&g_amax[bat * NSTAGE + s_id], key);
        }
        float4* dst = (float4*)(g_out + ((size_t)bat * Nn + n_in_b) * Hh + c0);
        dst[0] = make_float4(v[0], v[1], v[2], v[3]);
        dst[1] = make_float4(v[4], v[5], v[6], v[7]);
    }
}

// ---------------- pool: gather winners, LN1+relu -> zsum --------------------
__global__ __launch_bounds__(256)
void pool_kernel(const float* __restrict__ g1, const float* __restrict__ be1) {
    __shared__ float sbuf[8];
    const int bs = blockIdx.x;
    const int b = bs / NSTAGE;
    const int h = threadIdx.x;

    ull key = g_amax[bs];
    unsigned int n = 0xFFFFFFFFu - (unsigned int)(key & 0xFFFFFFFFull);
    if (n >= Nn) n = 0;

    const float o = g_out[((size_t)b * Nn + n) * Hh + h];

    float mean = block_sum256(o, sbuf) * (1.f / Hh);
    float d = o - mean;
    float var = block_sum256(d * d, sbuf) * (1.f / Hh);
    float z = fmaxf(d * rsqrtf(var + LN_EPS) * g1[h] + be1[h], 0.f);

    atomicAdd(&g_zsum[b * Hh + h], z);
}

// ---------------- layer 2 (row 0 only) + head -------------------------------
__global__ __launch_bounds__(256)
void final_kernel(const float* __restrict__ W2, const float* __restrict__ b2,
                  const float* __restrict__ g2, const float* __restrict__ be2,
                  const float* __restrict__ fcW, const float* __restrict__ fcb,
                  float* __restrict__ out) {
    __shared__ float zs[Hh];
    __shared__ float sbuf[8];
    const int b = blockIdx.x;
    const int h = threadIdx.x;

    zs[h] = g_zsum[b * Hh + h];
    __syncthreads();

    float acc = b2[h];
    #pragma unroll 8
    for (int k = 0; k < Hh; k++) acc += zs[k] * W2[k * Hh + h];

    float mean = block_sum256(acc, sbuf) * (1.f / Hh);
    float d = acc - mean;
    float var = block_sum256(d * d, sbuf) * (1.f / Hh);
    float y = fmaxf(d * rsqrtf(var + LN_EPS) * g2[h] + be2[h], 0.f);

    float p = block_sum256(y * fcW[h], sbuf);
    if (h == 0) out[b] = p + fcb[0];
}

// ---------------- launch -----------------------------------------------------
extern "C" void kernel_launch(void* const* d_in, const int* in_sizes, int n_in,
                              void* d_out, int out_size) {
    const float* adjacency = (const float*)d_in[0];
    const float* features  = (const float*)d_in[1];
    const int*   stage_ids = (const int*)  d_in[2];
    const float* W0  = (const float*)d_in[3];
    const float* b0  = (const float*)d_in[4];
    const float* b1  = (const float*)d_in[5];
    const float* W2  = (const float*)d_in[6];
    const float* b2  = (const float*)d_in[7];
    const float* g0  = (const float*)d_in[8];
    const float* be0 = (const float*)d_in[9];
    const float* g1  = (const float*)d_in[10];
    const float* be1 = (const float*)d_in[11];
    const float* g2  = (const float*)d_in[12];
    const float* be2 = (const float*)d_in[13];
    const float* fcW = (const float*)d_in[14];
    const float* fcb = (const float*)d_in[15];
    float* out = (float*)d_out;

    cudaFuncSetAttribute(gemm_mma,
                         cudaFuncAttributeMaxDynamicSharedMemorySize, SMEM_DYN);

    // init + W0 split/transpose
    init_kernel<<<(Bsz * Hh + 255) / 256, 256>>>();
    w0split_kernel<<<64, 256>>>(W0);

    // GEMM1: support = features @ W0 -> pre-split fp16 [b][h][node]
    gemm_mma<<<2048, 256, SMEM_DYN>>>(features, 0,
                                      nullptr, nullptr, nullptr, nullptr, nullptr);

    // GEMM2: x = adj[b] @ support[b] + b0, fused LN0/relu/+b1/score/argmax
    gemm_mma<<<2048, 256, SMEM_DYN>>>(adjacency, 1,
                                      b0, g0, be0, b1, stage_ids);

    // gather winners, LN1+relu, accumulate zsum
    pool_kernel<<<Bsz * NSTAGE, 256>>>(g1, be1);

    // layer 2 row 0 + head
    final_kernel<<<Bsz, 256>>>(W2, b2, g2, be2, fcW, fcb, out);
}

// round 17
// speedup vs baseline: 1.2171x; 1.2171x over previous
#include <cuda_runtime.h>
#include <cuda_fp16.h>
#include <cstdint>

// Problem constants
#define Bsz 256
#define Nn  512
#define Ff  256
#define Hh  256
#define NSTAGE 5
#define LN_EPS 1e-5f

typedef unsigned long long ull;
typedef unsigned short ushort_t;

// ---------------- scratch (device globals; no allocations allowed) ----------
__device__ __half g_supH[(size_t)Bsz * Hh * Nn];   // support hi, [b][h][node]
__device__ __half g_supL[(size_t)Bsz * Hh * Nn];   // support lo
__device__ __half g_w0H [Hh * Ff];                 // W0^T hi, [h][f]
__device__ __half g_w0L [Hh * Ff];
__device__ float  g_out [(size_t)Bsz * Nn * Hh];   // relu(LN0(x))+b1 rows
__device__ ull    g_amax[Bsz * NSTAGE];            // packed argmax keys
__device__ float  g_zsum[Bsz * Hh];

// ---------------- helpers ---------------------------------------------------
__device__ __forceinline__ unsigned int f2ord(float f) {
    unsigned int u = __float_as_uint(f);
    return (u & 0x80000000u) ? ~u : (u | 0x80000000u);
}

__device__ __forceinline__ uint32_t smem_u32(const void* p) {
    uint32_t a;
    asm("{ .reg .u64 t; cvta.to.shared.u64 t, %1; cvt.u32.u64 %0, t; }" : "=r"(a) : "l"(p));
    return a;
}

__device__ __forceinline__ void ldsm_x4(uint32_t& r0, uint32_t& r1,
                                        uint32_t& r2, uint32_t& r3, uint32_t addr) {
    asm volatile("ldmatrix.sync.aligned.m8n8.x4.shared.b16 {%0,%1,%2,%3}, [%4];"
                 : "=r"(r0), "=r"(r1), "=r"(r2), "=r"(r3) : "r"(addr));
}

__device__ __forceinline__ float block_sum256(float v, float* sbuf) {
    #pragma unroll
    for (int o = 16; o > 0; o >>= 1) v += __shfl_xor_sync(0xffffffffu, v, o);
    if ((threadIdx.x & 31) == 0) sbuf[threadIdx.x >> 5] = v;
    __syncthreads();
    float t = 0.f;
    if (threadIdx.x < 32) {
        t = (threadIdx.x < 8) ? sbuf[threadIdx.x] : 0.f;
        #pragma unroll
        for (int o = 4; o > 0; o >>= 1) t += __shfl_xor_sync(0xffffffffu, t, o);
        if (threadIdx.x == 0) sbuf[0] = t;
    }
    __syncthreads();
    t = sbuf[0];
    __syncthreads();
    return t;
}

// m16n8k16 f16 mma, fp32 accumulate
__device__ __forceinline__ void mma16816(float* c, const uint32_t* a,
                                         uint32_t b0, uint32_t b1) {
    asm volatile(
        "mma.sync.aligned.m16n8k16.row.col.f32.f16.f16.f32 "
        "{%0,%1,%2,%3}, {%4,%5,%6,%7}, {%8,%9}, {%0,%1,%2,%3};"
        : "+f"(c[0]), "+f"(c[1]), "+f"(c[2]), "+f"(c[3])
        : "r"(a[0]), "r"(a[1]), "r"(a[2]), "r"(a[3]), "r"(b0), "r"(b1));
}

// split one f32 into (hi fp16, lo fp16 = rn(x - hi))
__device__ __forceinline__ void split16(float x, ushort_t& h, ushort_t& l) {
    __half hh = __float2half_rn(x);
    float r = x - __half2float(hh);
    h = __half_as_ushort(hh);
    l = __half_as_ushort(__float2half_rn(r));
}

// ---------------- init / W0 split+transpose ---------------------------------
__global__ void init_kernel() {
    int i = blockIdx.x * blockDim.x + threadIdx.x;
    if (i < Bsz * Hh) g_zsum[i] = 0.f;
    if (i < Bsz * NSTAGE) g_amax[i] = 0ull;
}

__global__ void w0split_kernel(const float* __restrict__ W0) {
    __shared__ float t[32][33];
    int bx = blockIdx.x & 7;       // h tile
    int by = blockIdx.x >> 3;      // f tile
    int c = (threadIdx.x >> 5) * 4, d = threadIdx.x & 31;
    #pragma unroll
    for (int i = 0; i < 4; i++)
        t[c + i][d] = W0[(by * 32 + c + i) * Hh + bx * 32 + d];  // t[f_l][h_l]
    __syncthreads();
    #pragma unroll
    for (int i = 0; i < 4; i++) {
        float v = t[d][c + i];     // f_l=d, h_l=c+i
        ushort_t h, l;
        split16(v, h, l);
        int o = (bx * 32 + c + i) * Ff + by * 32 + d;
        g_w0H[o] = __ushort_as_half(h);
        g_w0L[o] = __ushort_as_half(l);
    }
}

// ---------------- HMMA split-fp16 GEMM (ldmatrix frag loads) -----------------
// Tile: BM=64 x BN=256 (full H), BK=32 halfs. 256 threads, 8 warps (2m x 4n).
// mode 0: C = features[131072,256] @ W0  -> g_supH/g_supL, [b][h][node] fp16
// mode 1: x = adj[b] @ support[b]        -> fused +b0, LN0, relu, +b1,
//         score+argmax, writes g_out.
//
// staging smem (pitch 20 words = 40 halfs per 32-half row):
//   A_HI @0      64*20*4  = 5120 B      A_LO @5120
//   B_HI @10240  256*20*4 = 20480 B     B_LO @30720    (end 51200)
// epilogue xs: mode1 [64][260] f32; mode0 [256][65] f32  (both 66560 B)
#define SMEM_DYN 66560
#define PW  20
#define PXS 260
#define AHI_W 0
#define ALO_W 1280
#define BHI_W 2560
#define BLO_W 7680

__global__ __launch_bounds__(256, 2)
void gemm_mma(const float* __restrict__ Aglob, int mode,
              const float* __restrict__ b0p, const float* __restrict__ g0p,
              const float* __restrict__ be0p, const float* __restrict__ b1p,
              const int* __restrict__ sidp)
{
    extern __shared__ char dynsm[];
    __shared__ float sPar[4][256];         // b0, g0, be0, b1 (mode 1)

    uint32_t* W  = (uint32_t*)dynsm;
    float*    xs = (float*)dynsm;
    const uint32_t sb32 = smem_u32(dynsm);

    const int tid  = threadIdx.x;
    const int wid  = tid >> 5;
    const int lane = tid & 31;
    const int g    = lane >> 2;
    const int tg   = lane & 3;
    const int mBase = (wid >> 2) * 32;     // 0 or 32
    const int nBase = (wid & 3) * 64;      // 0,64,128,192

    int K, bat, nrow0;
    const float*  Ap;
    const __half* BH;
    const __half* BL;
    int bstr;
    if (mode) {
        K = Nn;
        bat   = blockIdx.x >> 3;
        nrow0 = (blockIdx.x & 7) * 64;
        Ap = Aglob + ((size_t)bat * Nn + nrow0) * (size_t)Nn;
        BH = g_supH + (size_t)bat * Hh * Nn;
        BL = g_supL + (size_t)bat * Hh * Nn;
        bstr = Nn;
        sPar[0][tid] = b0p[tid];  sPar[1][tid] = g0p[tid];
        sPar[2][tid] = be0p[tid]; sPar[3][tid] = b1p[tid];
    } else {
        K = Ff;
        bat   = blockIdx.x >> 3;
        nrow0 = (blockIdx.x & 7) * 64;
        Ap = Aglob + (size_t)blockIdx.x * 64 * (size_t)Ff;
        BH = g_w0H;  BL = g_w0L;
        bstr = Ff;
    }

    // ldmatrix lane-address components
    const int aRowSel = lane & 15;          // m row within 16-row tile
    const int aKSel   = lane >> 4;          // 0/1 -> 16B k-halves
    const int bNSub   = lane & 7;           // n row within 8
    const int bPairSel= (lane >> 4) & 1;    // which n-tile of the pair
    const int bKSel   = (lane >> 3) & 1;    // b0/b1 16B k-half

    float acc[2][8][4];
    #pragma unroll
    for (int mt = 0; mt < 2; mt++)
        #pragma unroll
        for (int nt = 0; nt < 8; nt++)
            #pragma unroll
            for (int e = 0; e < 4; e++) acc[mt][nt][e] = 0.f;

    const int NCH = K >> 5;
    for (int c = 0; c < NCH; c++) {
        const int k0 = c << 5;
        __syncthreads();

        // ---- stage A 64x32 fp32 -> hi/lo halfs ----
        #pragma unroll
        for (int it = 0; it < 2; it++) {
            int idx = tid + (it << 8);
            int row = idx >> 3, kq = idx & 7;
            float4 v = *(const float4*)(Ap + (size_t)row * K + k0 + (kq << 2));
            ushort_t hx, lx, hy, ly, hz, lz, hw, lw;
            split16(v.x, hx, lx); split16(v.y, hy, ly);
            split16(v.z, hz, lz); split16(v.w, hw, lw);
            int w = row * PW + (kq << 1);
            W[AHI_W + w]     = (uint32_t)hx | ((uint32_t)hy << 16);
            W[AHI_W + w + 1] = (uint32_t)hz | ((uint32_t)hw << 16);
            W[ALO_W + w]     = (uint32_t)lx | ((uint32_t)ly << 16);
            W[ALO_W + w + 1] = (uint32_t)lz | ((uint32_t)lw << 16);
        }
        // ---- stage B 256x32: pure float4 copies of pre-split fp16 ----------
        #pragma unroll
        for (int it = 0; it < 4; it++) {
            int idx = tid + (it << 8);
            int h = idx >> 2, q = idx & 3;
            float4 vh = *((const float4*)(BH + (size_t)h * bstr + k0) + q);
            float4 vl = *((const float4*)(BL + (size_t)h * bstr + k0) + q);
            *(float4*)(W + BHI_W + h * PW + (q << 2)) = vh;
            *(float4*)(W + BLO_W + h * PW + (q << 2)) = vl;
        }
        __syncthreads();

        // ---- mma: 2 k16 steps, ldmatrix frag loads ----
        #pragma unroll
        for (int ks = 0; ks < 2; ks++) {
            const int kwW = ks << 3;       // k word offset within row

            // A frags: one x4 per (mt, set)
            uint32_t aH[2][4], aL[2][4];
            #pragma unroll
            for (int mt = 0; mt < 2; mt++) {
                uint32_t off = (uint32_t)((mBase + mt * 16 + aRowSel) * PW
                                          + kwW + aKSel * 4) * 4;
                ldsm_x4(aH[mt][0], aH[mt][1], aH[mt][2], aH[mt][3],
                        sb32 + AHI_W * 4 + off);
                ldsm_x4(aL[mt][0], aL[mt][1], aL[mt][2], aL[mt][3],
                        sb32 + ALO_W * 4 + off);
            }

            // B frags + MMAs per n-tile pair (keeps live regs bounded)
            #pragma unroll
            for (int np = 0; np < 4; np++) {
                uint32_t off = (uint32_t)((nBase + (np * 2 + bPairSel) * 8 + bNSub) * PW
                                          + kwW + bKSel * 4) * 4;
                uint32_t bh[4], bl[4];
                ldsm_x4(bh[0], bh[1], bh[2], bh[3], sb32 + BHI_W * 4 + off);
                ldsm_x4(bl[0], bl[1], bl[2], bl[3], sb32 + BLO_W * 4 + off);
                #pragma unroll
                for (int j = 0; j < 2; j++) {
                    const int nt = np * 2 + j;
                    const uint32_t bH0 = bh[2 * j], bH1 = bh[2 * j + 1];
                    const uint32_t bL0 = bl[2 * j], bL1 = bl[2 * j + 1];
                    #pragma unroll
                    for (int mt = 0; mt < 2; mt++) {
                        mma16816(acc[mt][nt], aH[mt], bH0, bH1);
                        mma16816(acc[mt][nt], aH[mt], bL0, bL1);
                        mma16816(acc[mt][nt], aL[mt], bH0, bH1);
                    }
                }
            }
        }
    }
    __syncthreads();                       // staging -> xs reuse

    if (!mode) {
        // dump acc transposed: xs[h][node] pitch 65
        #pragma unroll
        for (int mt = 0; mt < 2; mt++) {
            #pragma unroll
            for (int nt = 0; nt < 8; nt++) {
                int r0 = mBase + mt * 16 + g;
                int cc = nBase + nt * 8 + 2 * tg;
                xs[cc * 65 + r0]           = acc[mt][nt][0];
                xs[(cc + 1) * 65 + r0]     = acc[mt][nt][1];
                xs[cc * 65 + r0 + 8]       = acc[mt][nt][2];
                xs[(cc + 1) * 65 + r0 + 8] = acc[mt][nt][3];
            }
        }
        __syncthreads();
        // split + packed u32 stores to g_supH/g_supL [b][h][node]
        #pragma unroll 4
        for (int it = 0; it < 32; it++) {
            int idx = tid + (it << 8);
            int h = idx >> 5, np = idx & 31;
            float v0 = xs[h * 65 + 2 * np];
            float v1 = xs[h * 65 + 2 * np + 1];
            ushort_t h0, l0, h1, l1;
            split16(v0, h0, l0); split16(v1, h1, l1);
            size_t o = ((size_t)bat * Hh + h) * Nn + nrow0 + 2 * np;
            *(uint32_t*)(g_supH + o) = (uint32_t)h0 | ((uint32_t)h1 << 16);
            *(uint32_t*)(g_supL + o) = (uint32_t)l0 | ((uint32_t)l1 << 16);
        }
        return;
    }

    // mode 1: dump acc to xs[64][PXS], then fused epilogue
    #pragma unroll
    for (int mt = 0; mt < 2; mt++) {
        #pragma unroll
        for (int nt = 0; nt < 8; nt++) {
            int r0 = mBase + mt * 16 + g;
            int cc = nBase + nt * 8 + 2 * tg;
            xs[r0 * PXS + cc]           = acc[mt][nt][0];
            xs[r0 * PXS + cc + 1]       = acc[mt][nt][1];
            xs[(r0 + 8) * PXS + cc]     = acc[mt][nt][2];
            xs[(r0 + 8) * PXS + cc + 1] = acc[mt][nt][3];
        }
    }
    __syncthreads();

    const int c0 = lane * 8;
    #pragma unroll
    for (int j = 0; j < 8; j++) {
        const int r = wid * 8 + j;
        float v[8];
        float s = 0.f, q = 0.f;
        #pragma unroll
        for (int e = 0; e < 8; e++) {
            float x = xs[r * PXS + c0 + e] + sPar[0][c0 + e];
            v[e] = x;
            s += x; q += x * x;
        }
        #pragma unroll
        for (int o = 16; o > 0; o >>= 1) {
            s += __shfl_xor_sync(0xffffffffu, s, o);
            q += __shfl_xor_sync(0xffffffffu, q, o);
        }
        const float mean = s * (1.f / Hh);
        const float rstd = rsqrtf(q * (1.f / Hh) - mean * mean + LN_EPS);

        float sc = 0.f;
        #pragma unroll
        for (int e = 0; e < 8; e++) {
            const int cc = c0 + e;
            float y = fmaxf((v[e] - mean) * rstd * sPar[1][cc] + sPar[2][cc], 0.f)
                      + sPar[3][cc];
            v[e] = y;
            sc += y;
        }
        #pragma unroll
        for (int o = 16; o > 0; o >>= 1) sc += __shfl_xor_sync(0xffffffffu, sc, o);

        const int n_in_b = nrow0 + r;
        if (lane == 0) {
            const int s_id = sidp[bat * Nn + n_in_b];
            ull key = ((ull)f2ord(sc) << 32) |
                      (ull)(0xFFFFFFFFu - (unsigned)n_in_b);  // lower idx wins
            atomicMax(&g_amax[bat * NSTAGE + s_id], key);
        }
        float4* dst = (float4*)(g_out + ((size_t)bat * Nn + n_in_b) * Hh + c0);
        dst[0] = make_float4(v[0], v[1], v[2], v[3]);
        dst[1] = make_float4(v[4], v[5], v[6], v[7]);
    }
}

// ---------------- pool: gather winners, LN1+relu -> zsum --------------------
__global__ __launch_bounds__(256)
void pool_kernel(const float* __restrict__ g1, const float* __restrict__ be1) {
    __shared__ float sbuf[8];
    const int bs = blockIdx.x;
    const int b = bs / NSTAGE;
    const int h = threadIdx.x;

    ull key = g_amax[bs];
    unsigned int n = 0xFFFFFFFFu - (unsigned int)(key & 0xFFFFFFFFull);
    if (n >= Nn) n = 0;

    const float o = g_out[((size_t)b * Nn + n) * Hh + h];

    float mean = block_sum256(o, sbuf) * (1.f / Hh);
    float d = o - mean;
    float var = block_sum256(d * d, sbuf) * (1.f / Hh);
    float z = fmaxf(d * rsqrtf(var + LN_EPS) * g1[h] + be1[h], 0.f);

    atomicAdd(&g_zsum[b * Hh + h], z);
}

// ---------------- layer 2 (row 0 only) + head -------------------------------
__global__ __launch_bounds__(256)
void final_kernel(const float* __restrict__ W2, const float* __restrict__ b2,
                  const float* __restrict__ g2, const float* __restrict__ be2,
                  const float* __restrict__ fcW, const float* __restrict__ fcb,
                  float* __restrict__ out) {
    __shared__ float zs[Hh];
    __shared__ float sbuf[8];
    const int b = blockIdx.x;
    const int h = threadIdx.x;

    zs[h] = g_zsum[b * Hh + h];
    __syncthreads();

    float acc = b2[h];
    #pragma unroll 8
    for (int k = 0; k < Hh; k++) acc += zs[k] * W2[k * Hh + h];

    float mean = block_sum256(acc, sbuf) * (1.f / Hh);
    float d = acc - mean;
    float var = block_sum256(d * d, sbuf) * (1.f / Hh);
    float y = fmaxf(d * rsqrtf(var + LN_EPS) * g2[h] + be2[h], 0.f);

    float p = block_sum256(y * fcW[h], sbuf);
    if (h == 0) out[b] = p + fcb[0];
}

// ---------------- launch -----------------------------------------------------
extern "C" void kernel_launch(void* const* d_in, const int* in_sizes, int n_in,
                              void* d_out, int out_size) {
    const float* adjacency = (const float*)d_in[0];
    const float* features  = (const float*)d_in[1];
    const int*   stage_ids = (const int*)  d_in[2];
    const float* W0  = (const float*)d_in[3];
    const float* b0  = (const float*)d_in[4];
    const float* b1  = (const float*)d_in[5];
    const float* W2  = (const float*)d_in[6];
    const float* b2  = (const float*)d_in[7];
    const float* g0  = (const float*)d_in[8];
    const float* be0 = (const float*)d_in[9];
    const float* g1  = (const float*)d_in[10];
    const float* be1 = (const float*)d_in[11];
    const float* g2  = (const float*)d_in[12];
    const float* be2 = (const float*)d_in[13];
    const float* fcW = (const float*)d_in[14];
    const float* fcb = (const float*)d_in[15];
    float* out = (float*)d_out;

    cudaFuncSetAttribute(gemm_mma,
                         cudaFuncAttributeMaxDynamicSharedMemorySize, SMEM_DYN);

    // init + W0 split/transpose
    init_kernel<<<(Bsz * Hh + 255) / 256, 256>>>();
    w0split_kernel<<<64, 256>>>(W0);

    // GEMM1: support = features @ W0 -> pre-split fp16 [b][h][node]
    gemm_mma<<<2048, 256, SMEM_DYN>>>(features, 0,
                                      nullptr, nullptr, nullptr, nullptr, nullptr);

    // GEMM2: x = adj[b] @ support[b] + b0, fused LN0/relu/+b1/score/argmax
    gemm_mma<<<2048, 256, SMEM_DYN>>>(adjacency, 1,
                                      b0, g0, be0, b1, stage_ids);

    // gather winners, LN1+relu, accumulate zsum
    pool_kernel<<<Bsz * NSTAGE, 256>>>(g1, be1);

    // layer 2 row 0 + head
    final_kernel<<<Bsz, 256>>>(W2, b2, g2, be2, fcW, fcb, out);
}